// round 6
// baseline (speedup 1.0000x reference)
#include <cuda_runtime.h>
#include <stdint.h>

// InstantNGP hash-grid embedding — L1tex-wavefront-bound gather kernel.
// x: (B,3) fp32; embeddings: (16, 2^19, 2) fp32; out: (B, 32) fp32.
//
// Tricks:
//  * x-hash prime is 1 -> for even ix both x-corners live in one aligned
//    16B chunk -> single LDG.128 (branchless: odd ix weights partner 0 and
//    issues a predicated LDG.64 for its second corner).
//  * per-level results go straight to smem (no 32-reg accumulator array),
//    then coalesced float4 stores (halves store wavefronts, frees regs).

#define NLEV 16
#define TS   (1u << 19)
#define MSK  (TS - 1u)
#define P2   2654435761u
#define P3   805459861u

__global__ __launch_bounds__(256, 5) void hashgrid_kernel(
    const float* __restrict__ x,
    const float* __restrict__ emb,
    float* __restrict__ out,
    int B)
{
    constexpr int RES_TBL[NLEV] = {16, 20, 25, 32, 40, 50, 64, 80,
                                   101, 128, 161, 203, 256, 322, 406, 512};

    // One phase = 8 levels = 4 float4 per point. 257 stride: conflict-free
    // LDS.128 readback. 4*257*16B = 16448 B static smem.
    __shared__ float4 osm[4 * 257];

    const int tid = threadIdx.x;
    int i = blockIdx.x * 256 + tid;
    if (i >= B) i = B - 1;          // grid is exact for B=1M; clamp for safety

    const float x0 = __ldg(&x[3 * i + 0]);
    const float x1 = __ldg(&x[3 * i + 1]);
    const float x2 = __ldg(&x[3 * i + 2]);

    float4* out4 = reinterpret_cast<float4*>(out);

    #pragma unroll
    for (int ph = 0; ph < 2; ph++) {
        #pragma unroll
        for (int lk = 0; lk < 8; lk++) {
            const int   l   = ph * 8 + lk;
            const int   res = RES_TBL[l];
            const float s   = 0.5f * (float)res;

            const float r0 = (x0 + 1.0f) * s;
            const float r1 = (x1 + 1.0f) * s;
            const float r2 = (x2 + 1.0f) * s;

            const float f0 = fminf(fmaxf(floorf(r0), 0.0f), (float)(res - 1));
            const float f1 = fminf(fmaxf(floorf(r1), 0.0f), (float)(res - 1));
            const float f2 = fminf(fmaxf(floorf(r2), 0.0f), (float)(res - 1));

            const float w0 = r0 - f0, w1 = r1 - f1, w2 = r2 - f2;
            const float v0 = 1.0f - w0, v1 = 1.0f - w1, v2 = 1.0f - w2;

            const uint32_t ix = (uint32_t)f0;
            const uint32_t iy = (uint32_t)f1;
            const uint32_t iz = (uint32_t)f2;

            const uint32_t hy0 = iy * P2, hy1 = hy0 + P2;
            const uint32_t hz0 = iz * P3, hz1 = hz0 + P3;

            const bool  odd  = (ix & 1u) != 0u;
            const float w0e  = odd ? 0.0f : w0;   // partner-slot weight (even only)
            const uint32_t ixp = ix + 1u;

            const float2* __restrict__ tbl =
                reinterpret_cast<const float2*>(emb) + (size_t)l * TS;
            const float4* __restrict__ tbl4 =
                reinterpret_cast<const float4*>(tbl);

            float ax = 0.0f, ay = 0.0f;

            #pragma unroll
            for (int m = 0; m < 4; m++) {
                const uint32_t cyz = ((m & 1) ? hy1 : hy0) ^
                                     ((m & 2) ? hz1 : hz0);
                const float    wyz = ((m & 1) ? w1 : v1) *
                                     ((m & 2) ? w2 : v2);

                // chunk covering corner x=ix (and, for even ix, x=ix+1)
                const uint32_t hA = (ix ^ cyz) & MSK;
                const float wA = v0 * wyz;        // weight of slot hA
                const float wB = w0e * wyz;       // weight of slot hA^1
                const bool  swp = (hA & 1u) != 0u;
                const float wlo = swp ? wB : wA;
                const float whi = swp ? wA : wB;
                const float4 q = __ldg(tbl4 + (hA >> 1));
                ax = fmaf(wlo, q.x, fmaf(whi, q.z, ax));
                ay = fmaf(wlo, q.y, fmaf(whi, q.w, ay));

                if (odd) {                        // predicated second corner
                    const uint32_t h2 = (ixp ^ cyz) & MSK;
                    const float    wt = w0 * wyz;
                    const float2   vv = __ldg(tbl + h2);
                    ax = fmaf(wt, vv.x, ax);
                    ay = fmaf(wt, vv.y, ay);
                }
            }

            // stash (ax, ay) in smem: slot k = lk>>1, half = lk&1
            reinterpret_cast<float2*>(&osm[(lk >> 1) * 257 + tid])[lk & 1] =
                make_float2(ax, ay);
        }

        __syncthreads();

        // coalesced copy: 1024 float4 per block-phase, 4 per thread
        #pragma unroll
        for (int c = 0; c < 4; c++) {
            const int q  = c * 256 + tid;      // 0..1023
            const int pl = q >> 2;             // local point
            const int k  = q & 3;              // float4 slot within phase
            const size_t g = (size_t)blockIdx.x * 2048 +
                             (size_t)pl * 8 + ph * 4 + k;
            if (g < (size_t)B * 8) out4[g] = osm[k * 257 + pl];
        }

        __syncthreads();
    }
}

extern "C" void kernel_launch(void* const* d_in, const int* in_sizes, int n_in,
                              void* d_out, int out_size)
{
    const float* x   = (const float*)d_in[0];
    const float* emb = (const float*)d_in[1];
    float* out       = (float*)d_out;
    const int B      = in_sizes[0] / 3;

    const int threads = 256;
    const int blocks  = (B + threads - 1) / threads;
    hashgrid_kernel<<<blocks, threads>>>(x, emb, out, B);
}

// round 8
// speedup vs baseline: 1.0641x; 1.0641x over previous
#include <cuda_runtime.h>
#include <stdint.h>

// InstantNGP hash-grid embedding — L1tex-wavefront-bound gather kernel.
// x: (B,3) fp32; embeddings: (16, 2^19, 2) fp32; out: (B, 32) fp32.
//
// Levels 0-7 (res<=80): a prologue kernel builds a dense mirror grid where
// entry (ix,iy,iz) = (table[h(ix)], table[h(ix+1)]) as one aligned float4.
// Main kernel then does exactly 4 LDG.128 gathers per level, every lane.
// Levels 8-15: hash-table path; x-prime is 1 so even ix pairs both x-corners
// in one aligned 16B chunk (LDG.128), odd ix does 8 LDG.64.

#define NLEV 16
#define TS   (1u << 19)
#define MSK  (TS - 1u)
#define P2   2654435761u
#define P3   805459861u

#define NDENSE 8
#define DENSE_TOTAL 1075325  // sum over levels 0..7 of (res+1)^3

__device__ float4 g_dense[DENSE_TOTAL];   // 17.2 MB scratch

// res per level: floor(16 * 2^(i/3))
#define RES_LIST {16, 20, 25, 32, 40, 50, 64, 80, 101, 128, 161, 203, 256, 322, 406, 512}
// prefix offsets (float4 units) of dense levels 0..7, plus total
#define DOFF_LIST {0, 4913, 14174, 31750, 67687, 136608, 269259, 543884, DENSE_TOTAL}

__global__ __launch_bounds__(256) void fill_dense_kernel(
    const float* __restrict__ emb)
{
    constexpr int RES_TBL[NLEV] = RES_LIST;
    constexpr int DOFF[NDENSE + 1] = DOFF_LIST;

    const int idx = blockIdx.x * 256 + threadIdx.x;
    if (idx >= DENSE_TOTAL) return;

    // find level
    int l = 0;
    #pragma unroll
    for (int t = 1; t < NDENSE; t++)
        if (idx >= DOFF[t]) l = t;

    const int rem = idx - DOFF[l];
    const int R1  = RES_TBL[l] + 1;
    const int iz  = rem / (R1 * R1);
    const int r2  = rem - iz * R1 * R1;
    const int iy  = r2 / R1;
    const int ix  = r2 - iy * R1;

    const uint32_t hyz = (uint32_t)iy * P2 ^ (uint32_t)iz * P3;
    const uint32_t h0  = ((uint32_t)ix ^ hyz) & MSK;
    const uint32_t h1  = ((uint32_t)(ix + 1) ^ hyz) & MSK;

    const float2* __restrict__ tbl =
        reinterpret_cast<const float2*>(emb) + (size_t)l * TS;
    const float2 a = __ldg(tbl + h0);
    const float2 b = __ldg(tbl + h1);
    g_dense[idx] = make_float4(a.x, a.y, b.x, b.y);
}

__global__ __launch_bounds__(256) void hashgrid_kernel(
    const float* __restrict__ x,
    const float* __restrict__ emb,
    float* __restrict__ out,
    int B)
{
    constexpr int RES_TBL[NLEV] = RES_LIST;
    constexpr int DOFF[NDENSE + 1] = DOFF_LIST;

    const int i = blockIdx.x * blockDim.x + threadIdx.x;
    if (i >= B) return;

    const float x0 = x[3 * i + 0];
    const float x1 = x[3 * i + 1];
    const float x2 = x[3 * i + 2];

    float o[2 * NLEV];   // 32 output floats in registers (level loop unrolled)

    #pragma unroll
    for (int l = 0; l < NLEV; l++) {
        const int   res = RES_TBL[l];
        const float s   = 0.5f * (float)res;

        const float r0 = (x0 + 1.0f) * s;
        const float r1 = (x1 + 1.0f) * s;
        const float r2 = (x2 + 1.0f) * s;

        const float f0 = fminf(fmaxf(floorf(r0), 0.0f), (float)(res - 1));
        const float f1 = fminf(fmaxf(floorf(r1), 0.0f), (float)(res - 1));
        const float f2 = fminf(fmaxf(floorf(r2), 0.0f), (float)(res - 1));

        const float w0 = r0 - f0, w1 = r1 - f1, w2 = r2 - f2;
        const float v0 = 1.0f - w0, v1 = 1.0f - w1, v2 = 1.0f - w2;

        const uint32_t ix = (uint32_t)f0;
        const uint32_t iy = (uint32_t)f1;
        const uint32_t iz = (uint32_t)f2;

        float ax = 0.0f, ay = 0.0f;

        if (l < NDENSE) {
            // Dense mirror: 4 aligned LDG.128, both x-corners per load.
            const uint32_t R1  = (uint32_t)(res + 1);
            const uint32_t lin = ix + R1 * (iy + R1 * iz);
            const float4* __restrict__ dl = g_dense + DOFF[l];
            #pragma unroll
            for (int m = 0; m < 4; m++) {
                const uint32_t off = lin + ((m & 1) ? R1 : 0u) +
                                           ((m & 2) ? R1 * R1 : 0u);
                const float wyz = ((m & 1) ? w1 : v1) *
                                  ((m & 2) ? w2 : v2);
                const float4 q = __ldg(dl + off);
                ax = fmaf(wyz * v0, q.x, fmaf(wyz * w0, q.z, ax));
                ay = fmaf(wyz * v0, q.y, fmaf(wyz * w0, q.w, ay));
            }
        } else {
            const uint32_t hy0 = iy * P2, hy1 = hy0 + P2;
            const uint32_t hz0 = iz * P3, hz1 = hz0 + P3;

            const float2* __restrict__ tbl =
                reinterpret_cast<const float2*>(emb) + (size_t)l * TS;

            if ((ix & 1u) == 0u) {
                // Even ix: x-pair {h, h^1} in one aligned 16B chunk.
                const float4* __restrict__ tbl4 =
                    reinterpret_cast<const float4*>(tbl);
                #pragma unroll
                for (int m = 0; m < 4; m++) {
                    const uint32_t cyz = ((m & 1) ? hy1 : hy0) ^
                                         ((m & 2) ? hz1 : hz0);
                    const float    wyz = ((m & 1) ? w1 : v1) *
                                         ((m & 2) ? w2 : v2);
                    const uint32_t h0 = (ix ^ cyz) & MSK;
                    const float wx0 = v0 * wyz;
                    const float wx1 = w0 * wyz;
                    const bool  swp = (h0 & 1u) != 0u;
                    const float wlo = swp ? wx1 : wx0;
                    const float whi = swp ? wx0 : wx1;
                    const float4 q = __ldg(tbl4 + (h0 >> 1));
                    ax = fmaf(wlo, q.x, fmaf(whi, q.z, ax));
                    ay = fmaf(wlo, q.y, fmaf(whi, q.w, ay));
                }
            } else {
                const uint32_t hx0 = ix, hx1 = ix + 1u;
                #pragma unroll
                for (int k = 0; k < 8; k++) {
                    const uint32_t h = (((k & 1) ? hx1 : hx0) ^
                                        ((k & 2) ? hy1 : hy0) ^
                                        ((k & 4) ? hz1 : hz0)) & MSK;
                    const float wt = ((k & 1) ? w0 : v0) *
                                     ((k & 2) ? w1 : v1) *
                                     ((k & 4) ? w2 : v2);
                    const float2 vv = __ldg(tbl + h);
                    ax = fmaf(wt, vv.x, ax);
                    ay = fmaf(wt, vv.y, ay);
                }
            }
        }
        o[2 * l + 0] = ax;
        o[2 * l + 1] = ay;
    }

    // 8 x 16B contiguous stores per thread.
    float4* op = reinterpret_cast<float4*>(out + (size_t)i * (2 * NLEV));
    const float4* of = reinterpret_cast<const float4*>(o);
    #pragma unroll
    for (int j = 0; j < 8; j++) op[j] = of[j];
}

extern "C" void kernel_launch(void* const* d_in, const int* in_sizes, int n_in,
                              void* d_out, int out_size)
{
    const float* x   = (const float*)d_in[0];
    const float* emb = (const float*)d_in[1];
    float* out       = (float*)d_out;
    const int B      = in_sizes[0] / 3;

    fill_dense_kernel<<<(DENSE_TOTAL + 255) / 256, 256>>>(emb);

    const int threads = 256;
    const int blocks  = (B + threads - 1) / threads;
    hashgrid_kernel<<<blocks, threads>>>(x, emb, out, B);
}

// round 11
// speedup vs baseline: 1.2289x; 1.1548x over previous
#include <cuda_runtime.h>
#include <cuda_fp16.h>
#include <stdint.h>

// InstantNGP hash-grid embedding — L1tex-wavefront-bound gather kernel.
// x: (B,3) fp32; embeddings: (16, 2^19, 2) fp32; out: (B, 32) fp32.
//
// Model (verified R8): runtime ~= gather count x 1 cyc/SM wavefront service.
// So: minimize gathers.
//  * Levels 0-8: dense fp16 mirror, y-PAIRED layout. A 16B block at
//    (ix, yb, iz) holds slot0 = y=2yb, slot1 = y=2yb+1; each 8B slot is the
//    x-pair (val[ix], val[ix+1]) as 4 halves (scaled by 2^24).
//    Even iy: 2 x LDG.128 per level (4 corners per load).
//    Odd  iy: 4 x LDG.64.          -> avg 3 gathers/level.
//  * Levels 9-15: hash path. x-prime is 1, so even ix pairs both x-corners
//    in one aligned 16B chunk (4 x LDG.128); odd ix does 8 x LDG.64.
//                                   -> avg 6 gathers/level.

#define NLEV 16
#define TS   (1u << 19)
#define MSK  (TS - 1u)
#define P2   2654435761u
#define P3   805459861u

#define NDENSE 9
#define DENSE_BLOCKS 1076710          // sum over lvl 0..8 of R1*NB*R1
#define FSCALE     16777216.0f        // 2^24
#define FSCALE_INV 5.9604644775390625e-8f

__device__ uint4 g_dense[DENSE_BLOCKS];   // 17.2 MB scratch

#define RES_LIST  {16, 20, 25, 32, 40, 50, 64, 80, 101, 128, 161, 203, 256, 322, 406, 512}
#define DOFF_LIST {0, 2601, 7452, 16240, 34753, 70054, 137680, 277105, 546106, DENSE_BLOCKS}

static __device__ __forceinline__ uint32_t h2u(__half2 h) {
    return *reinterpret_cast<uint32_t*>(&h);
}

__global__ __launch_bounds__(256) void fill_dense_kernel(
    const float* __restrict__ emb)
{
    constexpr int RES_TBL[NLEV] = RES_LIST;
    constexpr int DOFF[NDENSE + 1] = DOFF_LIST;

    const int idx = blockIdx.x * 256 + threadIdx.x;
    if (idx >= DENSE_BLOCKS) return;

    int l = 0;
    #pragma unroll
    for (int t = 1; t < NDENSE; t++)
        if (idx >= DOFF[t]) l = t;

    const int rem = idx - DOFF[l];
    const int res = RES_TBL[l];
    const int R1  = res + 1;
    const int NB  = res / 2 + 1;
    const int ix  = rem % R1;
    const int t2  = rem / R1;
    const int yb  = t2 % NB;
    const int iz  = t2 / NB;

    const uint32_t hy0 = (uint32_t)(2 * yb) * P2;
    const uint32_t hy1 = hy0 + P2;
    const uint32_t hz  = (uint32_t)iz * P3;
    const uint32_t hx0 = (uint32_t)ix;
    const uint32_t hx1 = hx0 + 1u;

    const float2* __restrict__ tbl =
        reinterpret_cast<const float2*>(emb) + (size_t)l * TS;

    const float2 v00 = __ldg(tbl + ((hx0 ^ hy0 ^ hz) & MSK));
    const float2 v10 = __ldg(tbl + ((hx1 ^ hy0 ^ hz) & MSK));
    const float2 v01 = __ldg(tbl + ((hx0 ^ hy1 ^ hz) & MSK));
    const float2 v11 = __ldg(tbl + ((hx1 ^ hy1 ^ hz) & MSK));

    uint4 o;
    o.x = h2u(__floats2half2_rn(v00.x * FSCALE, v00.y * FSCALE));  // slot0: A (x)
    o.y = h2u(__floats2half2_rn(v10.x * FSCALE, v10.y * FSCALE));  // slot0: B (x+1)
    o.z = h2u(__floats2half2_rn(v01.x * FSCALE, v01.y * FSCALE));  // slot1: A
    o.w = h2u(__floats2half2_rn(v11.x * FSCALE, v11.y * FSCALE));  // slot1: B
    g_dense[idx] = o;
}

static __device__ __forceinline__ float2 u2f2(uint32_t u) {
    return __half22float2(*reinterpret_cast<__half2*>(&u));
}

__global__ __launch_bounds__(256) void hashgrid_kernel(
    const float* __restrict__ x,
    const float* __restrict__ emb,
    float* __restrict__ out,
    int B)
{
    constexpr int RES_TBL[NLEV] = RES_LIST;
    constexpr int DOFF[NDENSE + 1] = DOFF_LIST;

    const int i = blockIdx.x * blockDim.x + threadIdx.x;
    if (i >= B) return;

    const float x0 = x[3 * i + 0];
    const float x1 = x[3 * i + 1];
    const float x2 = x[3 * i + 2];

    float o[2 * NLEV];   // 32 output floats in registers (level loop unrolled)

    #pragma unroll
    for (int l = 0; l < NLEV; l++) {
        const int   res = RES_TBL[l];
        const float s   = 0.5f * (float)res;

        const float r0 = (x0 + 1.0f) * s;
        const float r1 = (x1 + 1.0f) * s;
        const float r2 = (x2 + 1.0f) * s;

        const float f0 = fminf(fmaxf(floorf(r0), 0.0f), (float)(res - 1));
        const float f1 = fminf(fmaxf(floorf(r1), 0.0f), (float)(res - 1));
        const float f2 = fminf(fmaxf(floorf(r2), 0.0f), (float)(res - 1));

        const float w0 = r0 - f0, w1 = r1 - f1, w2 = r2 - f2;
        const float v0 = 1.0f - w0, v1 = 1.0f - w1, v2 = 1.0f - w2;

        const uint32_t ix = (uint32_t)f0;
        const uint32_t iy = (uint32_t)f1;
        const uint32_t iz = (uint32_t)f2;

        float ax = 0.0f, ay = 0.0f;

        if (l < NDENSE) {
            const uint32_t R1 = (uint32_t)(res + 1);
            const uint32_t NB = (uint32_t)(res / 2 + 1);
            const uint32_t yb = iy >> 1, ys = iy & 1u;
            const uint32_t zs  = R1 * NB;                 // z stride (blocks)
            const uint32_t blk = ix + R1 * (yb + NB * iz);
            const uint4* __restrict__ dl = g_dense + DOFF[l];

            // corner-weight products (y0 = iy gets v1, y1 = iy+1 gets w1)
            const float pA = v0 * v1, pB = w0 * v1;
            const float pC = v0 * w1, pD = w0 * w1;

            #pragma unroll
            for (int zc = 0; zc < 2; zc++) {
                const float wz = (zc ? w2 : v2) * FSCALE_INV;
                float2 c0, c1, c2, c3;
                if (ys == 0u) {
                    // one 16B block holds both y corners x both x corners
                    const uint4 q = __ldg(dl + blk + zc * zs);
                    c0 = u2f2(q.x); c1 = u2f2(q.y);   // y = iy
                    c2 = u2f2(q.z); c3 = u2f2(q.w);   // y = iy+1
                } else {
                    const uint2* __restrict__ p =
                        reinterpret_cast<const uint2*>(dl);
                    const uint2 e0 = __ldg(p + 2u * (blk + zc * zs) + 1u);       // slot1: y=iy
                    const uint2 e1 = __ldg(p + 2u * (blk + R1 + zc * zs));       // slot0 of yb+1: y=iy+1
                    c0 = u2f2(e0.x); c1 = u2f2(e0.y);
                    c2 = u2f2(e1.x); c3 = u2f2(e1.y);
                }
                const float qA = wz * pA, qB = wz * pB;
                const float qC = wz * pC, qD = wz * pD;
                ax = fmaf(qA, c0.x, fmaf(qB, c1.x, fmaf(qC, c2.x, fmaf(qD, c3.x, ax))));
                ay = fmaf(qA, c0.y, fmaf(qB, c1.y, fmaf(qC, c2.y, fmaf(qD, c3.y, ay))));
            }
        } else {
            const uint32_t hy0 = iy * P2, hy1 = hy0 + P2;
            const uint32_t hz0 = iz * P3, hz1 = hz0 + P3;

            const float2* __restrict__ tbl =
                reinterpret_cast<const float2*>(emb) + (size_t)l * TS;

            if ((ix & 1u) == 0u) {
                // Even ix: x-pair {h, h^1} in one aligned 16B chunk.
                const float4* __restrict__ tbl4 =
                    reinterpret_cast<const float4*>(tbl);
                #pragma unroll
                for (int m = 0; m < 4; m++) {
                    const uint32_t cyz = ((m & 1) ? hy1 : hy0) ^
                                         ((m & 2) ? hz1 : hz0);
                    const float    wyz = ((m & 1) ? w1 : v1) *
                                         ((m & 2) ? w2 : v2);
                    const uint32_t h0 = (ix ^ cyz) & MSK;
                    const float wx0 = v0 * wyz;
                    const float wx1 = w0 * wyz;
                    const bool  swp = (h0 & 1u) != 0u;
                    const float wlo = swp ? wx1 : wx0;
                    const float whi = swp ? wx0 : wx1;
                    const float4 q = __ldg(tbl4 + (h0 >> 1));
                    ax = fmaf(wlo, q.x, fmaf(whi, q.z, ax));
                    ay = fmaf(wlo, q.y, fmaf(whi, q.w, ay));
                }
            } else {
                const uint32_t hx0 = ix, hx1 = ix + 1u;
                #pragma unroll
                for (int k = 0; k < 8; k++) {
                    const uint32_t h = (((k & 1) ? hx1 : hx0) ^
                                        ((k & 2) ? hy1 : hy0) ^
                                        ((k & 4) ? hz1 : hz0)) & MSK;
                    const float wt = ((k & 1) ? w0 : v0) *
                                     ((k & 2) ? w1 : v1) *
                                     ((k & 4) ? w2 : v2);
                    const float2 vv = __ldg(tbl + h);
                    ax = fmaf(wt, vv.x, ax);
                    ay = fmaf(wt, vv.y, ay);
                }
            }
        }
        o[2 * l + 0] = ax;
        o[2 * l + 1] = ay;
    }

    // 8 x 16B contiguous stores per thread.
    float4* op = reinterpret_cast<float4*>(out + (size_t)i * (2 * NLEV));
    const float4* of = reinterpret_cast<const float4*>(o);
    #pragma unroll
    for (int j = 0; j < 8; j++) op[j] = of[j];
}

extern "C" void kernel_launch(void* const* d_in, const int* in_sizes, int n_in,
                              void* d_out, int out_size)
{
    const float* x   = (const float*)d_in[0];
    const float* emb = (const float*)d_in[1];
    float* out       = (float*)d_out;
    const int B      = in_sizes[0] / 3;

    fill_dense_kernel<<<(DENSE_BLOCKS + 255) / 256, 256>>>(emb);

    const int threads = 256;
    const int blocks  = (B + threads - 1) / threads;
    hashgrid_kernel<<<blocks, threads>>>(x, emb, out, B);
}

// round 12
// speedup vs baseline: 1.3911x; 1.1320x over previous
#include <cuda_runtime.h>
#include <cuda_fp16.h>
#include <stdint.h>

// InstantNGP hash-grid embedding — L1tex-wavefront-bound gather kernel.
// x: (B,3) fp32; embeddings: (16, 2^19, 2) fp32; out: (B, 32) fp32.
//
// Model (verified R8/R11): runtime ~= gathers/point x 3.7us/M (divergent);
// prologue gathers are ix-coalesced (~1.5us/M). Minimize main-kernel gathers.
//
//  * Levels 0-8: dense fp16 mirror keyed (ix, iy, zb), REDUNDANT in y:
//    each 32B block = full 2x2x2 corner neighborhood (x-pair, y in {iy,iy+1},
//    z in {2zb, 2zb+1}), stored as two 16B z-halves (uint4 each; values
//    scaled by 2^24 so tiny table values are normal-range fp16).
//    Query reads its two needed z-halves -> exactly 2 LDG.128, any parity.
//  * Levels 9-15: hash path. x-prime is 1, so even ix pairs both x-corners
//    in one aligned 16B chunk (4 x LDG.128); odd ix does 8 x LDG.64.

#define NLEV 16
#define TS   (1u << 19)
#define MSK  (TS - 1u)
#define P2   2654435761u
#define P3   805459861u

#define NDENSE 9
#define DENSE_BLOCKS 1076710          // sum over lvl 0..8 of R1*R1*(res/2+1)
#define FSCALE     16777216.0f        // 2^24
#define FSCALE_INV 5.9604644775390625e-8f

__device__ uint4 g_dense[2 * DENSE_BLOCKS];   // 34.5 MB scratch (2 halves/block)

#define RES_LIST  {16, 20, 25, 32, 40, 50, 64, 80, 101, 128, 161, 203, 256, 322, 406, 512}
#define DOFF_LIST {0, 2601, 7452, 16240, 34753, 70054, 137680, 277105, 546106, DENSE_BLOCKS}

static __device__ __forceinline__ uint32_t h2u(__half2 h) {
    return *reinterpret_cast<uint32_t*>(&h);
}
static __device__ __forceinline__ float2 u2f2(uint32_t u) {
    return __half22float2(*reinterpret_cast<__half2*>(&u));
}

__global__ __launch_bounds__(256) void fill_dense_kernel(
    const float* __restrict__ emb)
{
    constexpr int RES_TBL[NLEV] = RES_LIST;
    constexpr int DOFF[NDENSE + 1] = DOFF_LIST;

    const int blk = blockIdx.x * 256 + threadIdx.x;
    if (blk >= DENSE_BLOCKS) return;

    int l = 0;
    #pragma unroll
    for (int t = 1; t < NDENSE; t++)
        if (blk >= DOFF[t]) l = t;

    const int rem = blk - DOFF[l];
    const int res = RES_TBL[l];
    const int R1  = res + 1;
    const int ix  = rem % R1;
    const int t2  = rem / R1;
    const int iy  = t2 % R1;
    const int zb  = t2 / R1;

    const uint32_t hx0 = (uint32_t)ix;
    const uint32_t hx1 = hx0 + 1u;
    const uint32_t hy0 = (uint32_t)iy * P2;
    const uint32_t hy1 = hy0 + P2;

    const float2* __restrict__ tbl =
        reinterpret_cast<const float2*>(emb) + (size_t)l * TS;

    #pragma unroll
    for (int h = 0; h < 2; h++) {
        const uint32_t hz = (uint32_t)(2 * zb + h) * P3;
        const float2 v00 = __ldg(tbl + ((hx0 ^ hy0 ^ hz) & MSK));
        const float2 v10 = __ldg(tbl + ((hx1 ^ hy0 ^ hz) & MSK));
        const float2 v01 = __ldg(tbl + ((hx0 ^ hy1 ^ hz) & MSK));
        const float2 v11 = __ldg(tbl + ((hx1 ^ hy1 ^ hz) & MSK));
        uint4 o;
        o.x = h2u(__floats2half2_rn(v00.x * FSCALE, v00.y * FSCALE));  // x0 y0
        o.y = h2u(__floats2half2_rn(v10.x * FSCALE, v10.y * FSCALE));  // x1 y0
        o.z = h2u(__floats2half2_rn(v01.x * FSCALE, v01.y * FSCALE));  // x0 y1
        o.w = h2u(__floats2half2_rn(v11.x * FSCALE, v11.y * FSCALE));  // x1 y1
        g_dense[2 * blk + h] = o;
    }
}

__global__ __launch_bounds__(256) void hashgrid_kernel(
    const float* __restrict__ x,
    const float* __restrict__ emb,
    float* __restrict__ out,
    int B)
{
    constexpr int RES_TBL[NLEV] = RES_LIST;
    constexpr int DOFF[NDENSE + 1] = DOFF_LIST;

    const int i = blockIdx.x * blockDim.x + threadIdx.x;
    if (i >= B) return;

    const float x0 = x[3 * i + 0];
    const float x1 = x[3 * i + 1];
    const float x2 = x[3 * i + 2];

    float o[2 * NLEV];   // 32 output floats in registers (level loop unrolled)

    #pragma unroll
    for (int l = 0; l < NLEV; l++) {
        const int   res = RES_TBL[l];
        const float s   = 0.5f * (float)res;

        const float r0 = (x0 + 1.0f) * s;
        const float r1 = (x1 + 1.0f) * s;
        const float r2 = (x2 + 1.0f) * s;

        const float f0 = fminf(fmaxf(floorf(r0), 0.0f), (float)(res - 1));
        const float f1 = fminf(fmaxf(floorf(r1), 0.0f), (float)(res - 1));
        const float f2 = fminf(fmaxf(floorf(r2), 0.0f), (float)(res - 1));

        const float w0 = r0 - f0, w1 = r1 - f1, w2 = r2 - f2;
        const float v0 = 1.0f - w0, v1 = 1.0f - w1, v2 = 1.0f - w2;

        const uint32_t ix = (uint32_t)f0;
        const uint32_t iy = (uint32_t)f1;
        const uint32_t iz = (uint32_t)f2;

        float ax = 0.0f, ay = 0.0f;

        if (l < NDENSE) {
            // Redundant-y, z-paired mirror: 2 LDG.128, branchless.
            const uint32_t R1  = (uint32_t)(res + 1);
            const uint32_t zs2 = 2u * R1 * R1;     // half-index stride per z-block
            const uint32_t blk = ix + R1 * (iy + R1 * (iz >> 1));
            const uint32_t odd = iz & 1u;
            const uint32_t base = 2u * blk;
            const uint32_t idx0 = base + odd;                     // z = iz
            const uint32_t idx1 = odd ? (base + zs2) : (base + 1u); // z = iz+1
            const uint4* __restrict__ dl = g_dense + 2 * DOFF[l];

            const float pA = v0 * v1, pB = w0 * v1;
            const float pC = v0 * w1, pD = w0 * w1;

            const uint4 q0 = __ldg(dl + idx0);
            const uint4 q1 = __ldg(dl + idx1);

            const float s0 = v2 * FSCALE_INV;
            const float s1 = w2 * FSCALE_INV;

            float2 c;
            c = u2f2(q0.x); ax = fmaf(s0 * pA, c.x, ax); ay = fmaf(s0 * pA, c.y, ay);
            c = u2f2(q0.y); ax = fmaf(s0 * pB, c.x, ax); ay = fmaf(s0 * pB, c.y, ay);
            c = u2f2(q0.z); ax = fmaf(s0 * pC, c.x, ax); ay = fmaf(s0 * pC, c.y, ay);
            c = u2f2(q0.w); ax = fmaf(s0 * pD, c.x, ax); ay = fmaf(s0 * pD, c.y, ay);
            c = u2f2(q1.x); ax = fmaf(s1 * pA, c.x, ax); ay = fmaf(s1 * pA, c.y, ay);
            c = u2f2(q1.y); ax = fmaf(s1 * pB, c.x, ax); ay = fmaf(s1 * pB, c.y, ay);
            c = u2f2(q1.z); ax = fmaf(s1 * pC, c.x, ax); ay = fmaf(s1 * pC, c.y, ay);
            c = u2f2(q1.w); ax = fmaf(s1 * pD, c.x, ax); ay = fmaf(s1 * pD, c.y, ay);
        } else {
            const uint32_t hy0 = iy * P2, hy1 = hy0 + P2;
            const uint32_t hz0 = iz * P3, hz1 = hz0 + P3;

            const float2* __restrict__ tbl =
                reinterpret_cast<const float2*>(emb) + (size_t)l * TS;

            if ((ix & 1u) == 0u) {
                // Even ix: x-pair {h, h^1} in one aligned 16B chunk.
                const float4* __restrict__ tbl4 =
                    reinterpret_cast<const float4*>(tbl);
                #pragma unroll
                for (int m = 0; m < 4; m++) {
                    const uint32_t cyz = ((m & 1) ? hy1 : hy0) ^
                                         ((m & 2) ? hz1 : hz0);
                    const float    wyz = ((m & 1) ? w1 : v1) *
                                         ((m & 2) ? w2 : v2);
                    const uint32_t h0 = (ix ^ cyz) & MSK;
                    const float wx0 = v0 * wyz;
                    const float wx1 = w0 * wyz;
                    const bool  swp = (h0 & 1u) != 0u;
                    const float wlo = swp ? wx1 : wx0;
                    const float whi = swp ? wx0 : wx1;
                    const float4 q = __ldg(tbl4 + (h0 >> 1));
                    ax = fmaf(wlo, q.x, fmaf(whi, q.z, ax));
                    ay = fmaf(wlo, q.y, fmaf(whi, q.w, ay));
                }
            } else {
                const uint32_t hx0 = ix, hx1 = ix + 1u;
                #pragma unroll
                for (int k = 0; k < 8; k++) {
                    const uint32_t h = (((k & 1) ? hx1 : hx0) ^
                                        ((k & 2) ? hy1 : hy0) ^
                                        ((k & 4) ? hz1 : hz0)) & MSK;
                    const float wt = ((k & 1) ? w0 : v0) *
                                     ((k & 2) ? w1 : v1) *
                                     ((k & 4) ? w2 : v2);
                    const float2 vv = __ldg(tbl + h);
                    ax = fmaf(wt, vv.x, ax);
                    ay = fmaf(wt, vv.y, ay);
                }
            }
        }
        o[2 * l + 0] = ax;
        o[2 * l + 1] = ay;
    }

    // 8 x 16B contiguous stores per thread.
    float4* op = reinterpret_cast<float4*>(out + (size_t)i * (2 * NLEV));
    const float4* of = reinterpret_cast<const float4*>(o);
    #pragma unroll
    for (int j = 0; j < 8; j++) op[j] = of[j];
}

extern "C" void kernel_launch(void* const* d_in, const int* in_sizes, int n_in,
                              void* d_out, int out_size)
{
    const float* x   = (const float*)d_in[0];
    const float* emb = (const float*)d_in[1];
    float* out       = (float*)d_out;
    const int B      = in_sizes[0] / 3;

    fill_dense_kernel<<<(DENSE_BLOCKS + 255) / 256, 256>>>(emb);

    const int threads = 256;
    const int blocks  = (B + threads - 1) / threads;
    hashgrid_kernel<<<blocks, threads>>>(x, emb, out, B);
}

// round 13
// speedup vs baseline: 1.4513x; 1.0433x over previous
#include <cuda_runtime.h>
#include <cuda_fp16.h>
#include <stdint.h>

// InstantNGP hash-grid embedding — L1tex/L2 sector-bound gather kernel.
// x: (B,3) fp32; embeddings: (16, 2^19, 2) fp32; out: (B, 32) fp32.
//
// Model (R8/R11/R12): runtime ~= sectors/point; gathers are the floor.
//  * Levels 0-8: dense fp16 mirror (prologue-built), keyed (ix,iy,zb),
//    redundant in y: 32B block = full 2x2x2 corner set as two 16B z-halves.
//    -> exactly 2 LDG.128 per level, branchless.
//  * Levels 9-15: hash path; x-prime is 1 so even ix pairs x-corners in one
//    aligned 16B chunk (4 LDG.128), odd ix does 8 LDG.64.
//  * 2 threads/point role split: role0 = levels 0-7, role1 = 8-15; each
//    stores 64B contiguous -> store sectors 8 -> 4 per point.

#define NLEV 16
#define TS   (1u << 19)
#define MSK  (TS - 1u)
#define P2   2654435761u
#define P3   805459861u

#define NDENSE 9
#define DENSE_BLOCKS 1076710          // sum over lvl 0..8 of R1*R1*(res/2+1)
#define FSCALE     16777216.0f        // 2^24
#define FSCALE_INV 5.9604644775390625e-8f

__device__ uint4 g_dense[2 * DENSE_BLOCKS];   // 34.5 MB scratch

#define RES_LIST  {16, 20, 25, 32, 40, 50, 64, 80, 101, 128, 161, 203, 256, 322, 406, 512}
#define DOFF_LIST {0, 2601, 7452, 16240, 34753, 70054, 137680, 277105, 546106, DENSE_BLOCKS}

static __device__ __forceinline__ uint32_t h2u(__half2 h) {
    return *reinterpret_cast<uint32_t*>(&h);
}
static __device__ __forceinline__ float2 u2f2(uint32_t u) {
    return __half22float2(*reinterpret_cast<__half2*>(&u));
}

__global__ __launch_bounds__(256) void fill_dense_kernel(
    const float* __restrict__ emb)
{
    constexpr int RES_TBL[NLEV] = RES_LIST;
    constexpr int DOFF[NDENSE + 1] = DOFF_LIST;

    const int blk = blockIdx.x * 256 + threadIdx.x;
    if (blk >= DENSE_BLOCKS) return;

    int l = 0;
    #pragma unroll
    for (int t = 1; t < NDENSE; t++)
        if (blk >= DOFF[t]) l = t;

    const int rem = blk - DOFF[l];
    const int res = RES_TBL[l];
    const int R1  = res + 1;
    const int ix  = rem % R1;
    const int t2  = rem / R1;
    const int iy  = t2 % R1;
    const int zb  = t2 / R1;

    const uint32_t hx0 = (uint32_t)ix;
    const uint32_t hx1 = hx0 + 1u;
    const uint32_t hy0 = (uint32_t)iy * P2;
    const uint32_t hy1 = hy0 + P2;

    const float2* __restrict__ tbl =
        reinterpret_cast<const float2*>(emb) + (size_t)l * TS;

    #pragma unroll
    for (int h = 0; h < 2; h++) {
        const uint32_t hz = (uint32_t)(2 * zb + h) * P3;
        const float2 v00 = __ldg(tbl + ((hx0 ^ hy0 ^ hz) & MSK));
        const float2 v10 = __ldg(tbl + ((hx1 ^ hy0 ^ hz) & MSK));
        const float2 v01 = __ldg(tbl + ((hx0 ^ hy1 ^ hz) & MSK));
        const float2 v11 = __ldg(tbl + ((hx1 ^ hy1 ^ hz) & MSK));
        uint4 o;
        o.x = h2u(__floats2half2_rn(v00.x * FSCALE, v00.y * FSCALE));  // x0 y0
        o.y = h2u(__floats2half2_rn(v10.x * FSCALE, v10.y * FSCALE));  // x1 y0
        o.z = h2u(__floats2half2_rn(v01.x * FSCALE, v01.y * FSCALE));  // x0 y1
        o.w = h2u(__floats2half2_rn(v11.x * FSCALE, v11.y * FSCALE));  // x1 y1
        g_dense[2 * blk + h] = o;
    }
}

template<int L>
static __device__ __forceinline__ float2 level_embed(
    float x0, float x1, float x2, const float* __restrict__ emb)
{
    constexpr int RES_TBL[NLEV] = RES_LIST;
    constexpr int DOFF[NDENSE + 1] = DOFF_LIST;
    constexpr int res = RES_TBL[L];
    const float s = 0.5f * (float)res;

    const float r0 = (x0 + 1.0f) * s;
    const float r1 = (x1 + 1.0f) * s;
    const float r2 = (x2 + 1.0f) * s;

    const float f0 = fminf(fmaxf(floorf(r0), 0.0f), (float)(res - 1));
    const float f1 = fminf(fmaxf(floorf(r1), 0.0f), (float)(res - 1));
    const float f2 = fminf(fmaxf(floorf(r2), 0.0f), (float)(res - 1));

    const float w0 = r0 - f0, w1 = r1 - f1, w2 = r2 - f2;
    const float v0 = 1.0f - w0, v1 = 1.0f - w1, v2 = 1.0f - w2;

    const uint32_t ix = (uint32_t)f0;
    const uint32_t iy = (uint32_t)f1;
    const uint32_t iz = (uint32_t)f2;

    float ax = 0.0f, ay = 0.0f;

    if (L < NDENSE) {
        // Redundant-y, z-paired mirror: 2 LDG.128, branchless.
        constexpr uint32_t R1  = (uint32_t)(res + 1);
        constexpr uint32_t zs2 = 2u * R1 * R1;
        const uint32_t blk  = ix + R1 * (iy + R1 * (iz >> 1));
        const uint32_t odd  = iz & 1u;
        const uint32_t base = 2u * blk;
        const uint32_t idx0 = base + odd;
        const uint32_t idx1 = odd ? (base + zs2) : (base + 1u);
        const uint4* __restrict__ dl = g_dense + 2 * DOFF[L];

        const float pA = v0 * v1, pB = w0 * v1;
        const float pC = v0 * w1, pD = w0 * w1;

        const uint4 q0 = __ldg(dl + idx0);
        const uint4 q1 = __ldg(dl + idx1);

        const float s0 = v2 * FSCALE_INV;
        const float s1 = w2 * FSCALE_INV;

        float2 c;
        c = u2f2(q0.x); ax = fmaf(s0 * pA, c.x, ax); ay = fmaf(s0 * pA, c.y, ay);
        c = u2f2(q0.y); ax = fmaf(s0 * pB, c.x, ax); ay = fmaf(s0 * pB, c.y, ay);
        c = u2f2(q0.z); ax = fmaf(s0 * pC, c.x, ax); ay = fmaf(s0 * pC, c.y, ay);
        c = u2f2(q0.w); ax = fmaf(s0 * pD, c.x, ax); ay = fmaf(s0 * pD, c.y, ay);
        c = u2f2(q1.x); ax = fmaf(s1 * pA, c.x, ax); ay = fmaf(s1 * pA, c.y, ay);
        c = u2f2(q1.y); ax = fmaf(s1 * pB, c.x, ax); ay = fmaf(s1 * pB, c.y, ay);
        c = u2f2(q1.z); ax = fmaf(s1 * pC, c.x, ax); ay = fmaf(s1 * pC, c.y, ay);
        c = u2f2(q1.w); ax = fmaf(s1 * pD, c.x, ax); ay = fmaf(s1 * pD, c.y, ay);
    } else {
        const uint32_t hy0 = iy * P2, hy1 = hy0 + P2;
        const uint32_t hz0 = iz * P3, hz1 = hz0 + P3;

        const float2* __restrict__ tbl =
            reinterpret_cast<const float2*>(emb) + (size_t)L * TS;

        if ((ix & 1u) == 0u) {
            const float4* __restrict__ tbl4 =
                reinterpret_cast<const float4*>(tbl);
            #pragma unroll
            for (int m = 0; m < 4; m++) {
                const uint32_t cyz = ((m & 1) ? hy1 : hy0) ^
                                     ((m & 2) ? hz1 : hz0);
                const float    wyz = ((m & 1) ? w1 : v1) *
                                     ((m & 2) ? w2 : v2);
                const uint32_t h0 = (ix ^ cyz) & MSK;
                const float wx0 = v0 * wyz;
                const float wx1 = w0 * wyz;
                const bool  swp = (h0 & 1u) != 0u;
                const float wlo = swp ? wx1 : wx0;
                const float whi = swp ? wx0 : wx1;
                const float4 q = __ldg(tbl4 + (h0 >> 1));
                ax = fmaf(wlo, q.x, fmaf(whi, q.z, ax));
                ay = fmaf(wlo, q.y, fmaf(whi, q.w, ay));
            }
        } else {
            const uint32_t hx0 = ix, hx1 = ix + 1u;
            #pragma unroll
            for (int k = 0; k < 8; k++) {
                const uint32_t h = (((k & 1) ? hx1 : hx0) ^
                                    ((k & 2) ? hy1 : hy0) ^
                                    ((k & 4) ? hz1 : hz0)) & MSK;
                const float wt = ((k & 1) ? w0 : v0) *
                                 ((k & 2) ? w1 : v1) *
                                 ((k & 4) ? w2 : v2);
                const float2 vv = __ldg(tbl + h);
                ax = fmaf(wt, vv.x, ax);
                ay = fmaf(wt, vv.y, ay);
            }
        }
    }
    return make_float2(ax, ay);
}

__global__ __launch_bounds__(256) void hashgrid_kernel(
    const float* __restrict__ x,
    const float* __restrict__ emb,
    float* __restrict__ out,
    int B)
{
    const int t = blockIdx.x * 256 + threadIdx.x;
    const int p = t >> 1;
    if (p >= B) return;
    const int role = t & 1;

    const float x0 = x[3 * p + 0];
    const float x1 = x[3 * p + 1];
    const float x2 = x[3 * p + 2];

    float4 of[4];
    if (role == 0) {
        const float2 e0 = level_embed<0>(x0, x1, x2, emb);
        const float2 e1 = level_embed<1>(x0, x1, x2, emb);
        const float2 e2 = level_embed<2>(x0, x1, x2, emb);
        const float2 e3 = level_embed<3>(x0, x1, x2, emb);
        const float2 e4 = level_embed<4>(x0, x1, x2, emb);
        const float2 e5 = level_embed<5>(x0, x1, x2, emb);
        const float2 e6 = level_embed<6>(x0, x1, x2, emb);
        const float2 e7 = level_embed<7>(x0, x1, x2, emb);
        of[0] = make_float4(e0.x, e0.y, e1.x, e1.y);
        of[1] = make_float4(e2.x, e2.y, e3.x, e3.y);
        of[2] = make_float4(e4.x, e4.y, e5.x, e5.y);
        of[3] = make_float4(e6.x, e6.y, e7.x, e7.y);
    } else {
        const float2 e0 = level_embed< 8>(x0, x1, x2, emb);
        const float2 e1 = level_embed< 9>(x0, x1, x2, emb);
        const float2 e2 = level_embed<10>(x0, x1, x2, emb);
        const float2 e3 = level_embed<11>(x0, x1, x2, emb);
        const float2 e4 = level_embed<12>(x0, x1, x2, emb);
        const float2 e5 = level_embed<13>(x0, x1, x2, emb);
        const float2 e6 = level_embed<14>(x0, x1, x2, emb);
        const float2 e7 = level_embed<15>(x0, x1, x2, emb);
        of[0] = make_float4(e0.x, e0.y, e1.x, e1.y);
        of[1] = make_float4(e2.x, e2.y, e3.x, e3.y);
        of[2] = make_float4(e4.x, e4.y, e5.x, e5.y);
        of[3] = make_float4(e6.x, e6.y, e7.x, e7.y);
    }

    // 64B contiguous per thread; adjacent threads fill one 128B output row.
    float4* op = reinterpret_cast<float4*>(out) + (size_t)p * 8 + role * 4;
    #pragma unroll
    for (int j = 0; j < 4; j++) op[j] = of[j];
}

extern "C" void kernel_launch(void* const* d_in, const int* in_sizes, int n_in,
                              void* d_out, int out_size)
{
    const float* x   = (const float*)d_in[0];
    const float* emb = (const float*)d_in[1];
    float* out       = (float*)d_out;
    const int B      = in_sizes[0] / 3;

    fill_dense_kernel<<<(DENSE_BLOCKS + 255) / 256, 256>>>(emb);

    const long long total = 2LL * B;
    const int threads = 256;
    const int blocks  = (int)((total + threads - 1) / threads);
    hashgrid_kernel<<<blocks, threads>>>(x, emb, out, B);
}